// round 1
// baseline (speedup 1.0000x reference)
#include <cuda_runtime.h>

#define B_    16
#define CIN_  256
#define COUT_ 3
#define WDIM_ 512
#define INS   128
#define OUTS  256
#define FW    13

// scratch (allocation-free rule: __device__ globals)
__device__ float g_c[B_ * COUT_ * CIN_];          // combined per-(b,o,i) weight
__device__ float g_kf[FW];                        // 2 * reversed filter
__device__ float g_mid[B_ * COUT_ * INS * INS];   // post 1x1 conv + clamp
__device__ float g_tmp[B_ * COUT_ * INS * OUTS];  // after horizontal upsample

// ---------------------------------------------------------------------------
// K1: styles + combined weights + filter prep
// grid (16 b, 8 i-groups), 256 threads (8 warps, 4 i per warp)
__global__ void k_styles(const float* __restrict__ w,
                         const float* __restrict__ aw,
                         const float* __restrict__ abias,
                         const float* __restrict__ cw,
                         const float* __restrict__ filt) {
    int b    = blockIdx.x;
    int warp = threadIdx.x >> 5;
    int lane = threadIdx.x & 31;
    const float* wr = w + (size_t)b * WDIM_;
    #pragma unroll
    for (int ii = 0; ii < 4; ii++) {
        int i = blockIdx.y * 32 + warp * 4 + ii;
        const float* awr = aw + (size_t)i * WDIM_;
        float s = 0.f;
        #pragma unroll
        for (int j = lane; j < WDIM_; j += 32)
            s += wr[j] * awr[j];
        #pragma unroll
        for (int off = 16; off; off >>= 1)
            s += __shfl_down_sync(0xffffffffu, s, off);
        if (lane == 0) {
            float style = (s * 0.04419417382415922f /*1/sqrt(512)*/ + abias[i])
                          * 0.0625f /*1/sqrt(256)*/;
            #pragma unroll
            for (int o = 0; o < COUT_; o++)
                g_c[(b * COUT_ + o) * CIN_ + i] = cw[o * CIN_ + i] * style;
        }
    }
    if (blockIdx.x == 0 && blockIdx.y == 0 && threadIdx.x < FW)
        g_kf[threadIdx.x] = 2.0f * filt[FW - 1 - threadIdx.x];
}

// ---------------------------------------------------------------------------
// K2: y[b,o,p] = clip(sum_i x[b,i,p]*c[b,o,i] + bias[o], +-256)
// grid (16 pixel-tiles, 16 b), 256 threads, float4 per thread (1024 px/block)
__global__ void k_einsum(const float* __restrict__ x,
                         const float* __restrict__ cbias) {
    const int b    = blockIdx.y;
    const int base = blockIdx.x * 1024 + threadIdx.x * 4;

    __shared__ float c_sm[COUT_ * CIN_];
    for (int t = threadIdx.x; t < COUT_ * CIN_; t += 256)
        c_sm[t] = g_c[b * COUT_ * CIN_ + t];
    __syncthreads();

    float4 a0 = make_float4(0.f, 0.f, 0.f, 0.f);
    float4 a1 = a0, a2 = a0;

    const float4* xp = (const float4*)(x + (size_t)b * CIN_ * INS * INS);
    #pragma unroll 4
    for (int i = 0; i < CIN_; i++) {
        float4 v = xp[(i * (INS * INS) + base) >> 2];
        float c0 = c_sm[i];
        float c1 = c_sm[CIN_ + i];
        float c2 = c_sm[2 * CIN_ + i];
        a0.x += c0 * v.x; a0.y += c0 * v.y; a0.z += c0 * v.z; a0.w += c0 * v.w;
        a1.x += c1 * v.x; a1.y += c1 * v.y; a1.z += c1 * v.z; a1.w += c1 * v.w;
        a2.x += c2 * v.x; a2.y += c2 * v.y; a2.z += c2 * v.z; a2.w += c2 * v.w;
    }

    float4* mp = (float4*)g_mid;
    float4 accs[3] = {a0, a1, a2};
    #pragma unroll
    for (int o = 0; o < COUT_; o++) {
        float bia = cbias[o];
        float4 r = accs[o];
        r.x = fminf(fmaxf(r.x + bia, -256.f), 256.f);
        r.y = fminf(fmaxf(r.y + bia, -256.f), 256.f);
        r.z = fminf(fmaxf(r.z + bia, -256.f), 256.f);
        r.w = fminf(fmaxf(r.w + bia, -256.f), 256.f);
        mp[(((size_t)(b * COUT_ + o)) * (INS * INS) + base) >> 2] = r;
    }
}

// ---------------------------------------------------------------------------
// K3a: horizontal polyphase upsample x2, 13-tap -> even phase 6 taps, odd 7
// grid (128 rows, 48 planes), 256 threads = output columns
__global__ void k_up_h() {
    const int plane = blockIdx.y;
    const int row   = blockIdx.x;
    const int n     = threadIdx.x;

    __shared__ float srow[INS];
    __shared__ float kf[FW];
    if (threadIdx.x < FW) kf[threadIdx.x] = g_kf[threadIdx.x];
    const float* in = g_mid + ((size_t)plane * INS + row) * INS;
    if (threadIdx.x < INS) srow[threadIdx.x] = in[threadIdx.x];
    __syncthreads();

    float acc = 0.f;
    if ((n & 1) == 0) {
        int s = n >> 1;
        #pragma unroll
        for (int j = 0; j < 6; j++) {
            int idx = s - 3 + j;
            if (idx >= 0 && idx < INS) acc += kf[2 * j + 1] * srow[idx];
        }
    } else {
        int s = (n - 1) >> 1;
        #pragma unroll
        for (int j = 0; j < 7; j++) {
            int idx = s - 3 + j;
            if (idx >= 0 && idx < INS) acc += kf[2 * j] * srow[idx];
        }
    }
    g_tmp[((size_t)plane * INS + row) * OUTS + n] = acc;
}

// ---------------------------------------------------------------------------
// K3b: vertical polyphase upsample x2
// grid (256 out rows, 48 planes), 256 threads = columns
__global__ void k_up_v(float* __restrict__ out) {
    const int plane = blockIdx.y;
    const int n     = blockIdx.x;   // output row
    const int col   = threadIdx.x;

    __shared__ float kf[FW];
    if (threadIdx.x < FW) kf[threadIdx.x] = g_kf[threadIdx.x];
    __syncthreads();

    const float* tp = g_tmp + (size_t)plane * INS * OUTS;
    float acc = 0.f;
    if ((n & 1) == 0) {
        int s = n >> 1;
        #pragma unroll
        for (int j = 0; j < 6; j++) {
            int idx = s - 3 + j;
            if (idx >= 0 && idx < INS) acc += kf[2 * j + 1] * tp[idx * OUTS + col];
        }
    } else {
        int s = (n - 1) >> 1;
        #pragma unroll
        for (int j = 0; j < 7; j++) {
            int idx = s - 3 + j;
            if (idx >= 0 && idx < INS) acc += kf[2 * j] * tp[idx * OUTS + col];
        }
    }
    out[((size_t)plane * OUTS + n) * OUTS + col] = acc;
}

// ---------------------------------------------------------------------------
extern "C" void kernel_launch(void* const* d_in, const int* in_sizes, int n_in,
                              void* d_out, int out_size) {
    const float* x     = (const float*)d_in[0];  // [16,256,128,128]
    const float* w     = (const float*)d_in[1];  // [16,512]
    const float* aw    = (const float*)d_in[2];  // [256,512]
    const float* ab    = (const float*)d_in[3];  // [256]
    const float* cw    = (const float*)d_in[4];  // [3,256,1,1]
    const float* cb    = (const float*)d_in[5];  // [3]
    const float* filt  = (const float*)d_in[6];  // [13]
    float* out = (float*)d_out;                  // [16,3,256,256]

    k_styles<<<dim3(B_, 8), 256>>>(w, aw, ab, cw, filt);
    k_einsum<<<dim3(16, B_), 256>>>(x, cb);
    k_up_h<<<dim3(INS, B_ * COUT_), 256>>>();
    k_up_v<<<dim3(OUTS, B_ * COUT_), 256>>>(out);
}

// round 3
// speedup vs baseline: 1.1824x; 1.1824x over previous
#include <cuda_runtime.h>

#define B_    16
#define CIN_  256
#define COUT_ 3
#define WDIM_ 512
#define INS   128
#define OUTS  256
#define FW    13
#define TR    16      // output rows per upsample tile
#define IR    14      // input rows needed per tile (TR/2 + 6)

// scratch (allocation-free rule: __device__ globals)
__device__ float g_c[B_ * COUT_ * CIN_];          // combined per-(b,o,i) weight
__device__ float g_kf[FW];                        // 2 * reversed filter
__device__ float g_mid[B_ * COUT_ * INS * INS];   // post 1x1 conv + clamp

// ---------------------------------------------------------------------------
// K1: styles + combined weights + filter prep
__global__ void k_styles(const float* __restrict__ w,
                         const float* __restrict__ aw,
                         const float* __restrict__ abias,
                         const float* __restrict__ cw,
                         const float* __restrict__ filt) {
    int b    = blockIdx.x;
    int warp = threadIdx.x >> 5;
    int lane = threadIdx.x & 31;
    const float* wr = w + (size_t)b * WDIM_;
    #pragma unroll
    for (int ii = 0; ii < 4; ii++) {
        int i = blockIdx.y * 32 + warp * 4 + ii;
        const float* awr = aw + (size_t)i * WDIM_;
        float s = 0.f;
        #pragma unroll
        for (int j = lane; j < WDIM_; j += 32)
            s += wr[j] * awr[j];
        #pragma unroll
        for (int off = 16; off; off >>= 1)
            s += __shfl_down_sync(0xffffffffu, s, off);
        if (lane == 0) {
            float style = (s * 0.04419417382415922f /*1/sqrt(512)*/ + abias[i])
                          * 0.0625f /*1/sqrt(256)*/;
            #pragma unroll
            for (int o = 0; o < COUT_; o++)
                g_c[(b * COUT_ + o) * CIN_ + i] = cw[o * CIN_ + i] * style;
        }
    }
    if (blockIdx.x == 0 && blockIdx.y == 0 && threadIdx.x < FW)
        g_kf[threadIdx.x] = 2.0f * filt[FW - 1 - threadIdx.x];
}

// ---------------------------------------------------------------------------
// K2: y[b,o,p] = clip(sum_i x[b,i,p]*c[b,o,i] + bias[o], +-256)
// grid (16 pixel-tiles, 16 b), 256 threads, float4 per thread (1024 px/block)
// unroll 8 on the channel loop -> MLP ~8 per thread, HBM-saturating.
__global__ void k_einsum(const float* __restrict__ x,
                         const float* __restrict__ cbias) {
    const int b    = blockIdx.y;
    const int base = blockIdx.x * 1024 + threadIdx.x * 4;

    __shared__ float c_sm[COUT_ * CIN_];
    for (int t = threadIdx.x; t < (COUT_ * CIN_) / 4; t += 256)
        ((float4*)c_sm)[t] = ((const float4*)(g_c + b * COUT_ * CIN_))[t];
    __syncthreads();

    float4 a0 = make_float4(0.f, 0.f, 0.f, 0.f);
    float4 a1 = a0, a2 = a0;

    const float* xb = x + (size_t)b * CIN_ * INS * INS + base;
    #pragma unroll 8
    for (int i = 0; i < CIN_; i++) {
        float4 v = *(const float4*)(xb + i * (INS * INS));
        float c0 = c_sm[i];
        float c1 = c_sm[CIN_ + i];
        float c2 = c_sm[2 * CIN_ + i];
        a0.x += c0 * v.x; a0.y += c0 * v.y; a0.z += c0 * v.z; a0.w += c0 * v.w;
        a1.x += c1 * v.x; a1.y += c1 * v.y; a1.z += c1 * v.z; a1.w += c1 * v.w;
        a2.x += c2 * v.x; a2.y += c2 * v.y; a2.z += c2 * v.z; a2.w += c2 * v.w;
    }

    float4* mp = (float4*)g_mid;
    float4 accs[3] = {a0, a1, a2};
    #pragma unroll
    for (int o = 0; o < COUT_; o++) {
        float bia = cbias[o];
        float4 r = accs[o];
        r.x = fminf(fmaxf(r.x + bia, -256.f), 256.f);
        r.y = fminf(fmaxf(r.y + bia, -256.f), 256.f);
        r.z = fminf(fmaxf(r.z + bia, -256.f), 256.f);
        r.w = fminf(fmaxf(r.w + bia, -256.f), 256.f);
        mp[(((size_t)(b * COUT_ + o)) * (INS * INS) + base) >> 2] = r;
    }
}

// ---------------------------------------------------------------------------
// K3: fused separable polyphase x2 upsample (H then V, all in shared memory).
// grid (48 planes, 16 row-tiles), 256 threads.
// Tap identity: for output index n (either axis), source base = (n>>1)-3 for
// BOTH parities; even phase weights kf[1,3,..,11] (6 taps), odd kf[0,2,..,12].
__global__ void k_upfused(float* __restrict__ out) {
    const int plane = blockIdx.x;
    const int tile  = blockIdx.y;
    const int r0    = tile * TR;     // first output row
    const int s0    = r0 >> 1;       // first "center" input row
    const int tid   = threadIdx.x;

    __shared__ float kf[FW];
    __shared__ float in_s[IR][INS];
    __shared__ float h_s[IR][OUTS];

    if (tid < FW) kf[tid] = g_kf[tid];

    // stage input rows s0-3 .. s0+10 (zero outside [0,128))
    const float* mp = g_mid + (size_t)plane * INS * INS;
    #pragma unroll
    for (int idx = tid; idx < IR * INS; idx += 256) {
        int r  = idx >> 7;
        int c  = idx & (INS - 1);
        int gr = s0 - 3 + r;
        in_s[r][c] = (gr >= 0 && gr < INS) ? mp[gr * INS + c] : 0.f;
    }
    __syncthreads();

    // ---- horizontal: col n = tid, all IR rows ----
    {
        const int n   = tid;
        const int par = n & 1;
        const int cb  = (n >> 1) - 3;
        float wt[7];
        int   cc[7];
        #pragma unroll
        for (int j = 0; j < 7; j++) {
            int c   = cb + j;
            float v = par ? kf[2 * j] : ((j < 6) ? kf[2 * j + 1] : 0.f);
            bool ok = (c >= 0 && c < INS);
            cc[j] = ok ? c : 0;
            wt[j] = ok ? v : 0.f;
        }
        #pragma unroll
        for (int r = 0; r < IR; r++) {
            float acc = 0.f;
            #pragma unroll
            for (int j = 0; j < 7; j++)
                acc += wt[j] * in_s[r][cc[j]];
            h_s[r][n] = acc;
        }
    }
    __syncthreads();

    // ---- vertical: col = tid, TR output rows ----
    float* op = out + ((size_t)plane * OUTS + r0) * OUTS + tid;
    #pragma unroll
    for (int k = 0; k < TR; k++) {
        const int n2  = r0 + k;
        const int lrb = (n2 >> 1) - s0;   // local base row in h_s
        float acc = 0.f;
        if (n2 & 1) {
            #pragma unroll
            for (int j = 0; j < 7; j++)
                acc += kf[2 * j] * h_s[lrb + j][tid];
        } else {
            #pragma unroll
            for (int j = 0; j < 6; j++)
                acc += kf[2 * j + 1] * h_s[lrb + j][tid];
        }
        op[k * OUTS] = acc;
    }
}

// ---------------------------------------------------------------------------
extern "C" void kernel_launch(void* const* d_in, const int* in_sizes, int n_in,
                              void* d_out, int out_size) {
    const float* x     = (const float*)d_in[0];  // [16,256,128,128]
    const float* w     = (const float*)d_in[1];  // [16,512]
    const float* aw    = (const float*)d_in[2];  // [256,512]
    const float* ab    = (const float*)d_in[3];  // [256]
    const float* cw    = (const float*)d_in[4];  // [3,256,1,1]
    const float* cb    = (const float*)d_in[5];  // [3]
    const float* filt  = (const float*)d_in[6];  // [13]
    float* out = (float*)d_out;                  // [16,3,256,256]

    k_styles<<<dim3(B_, 8), 256>>>(w, aw, ab, cw, filt);
    k_einsum<<<dim3(16, B_), 256>>>(x, cb);
    k_upfused<<<dim3(B_ * COUT_, OUTS / TR), 256>>>(out);
}